// round 16
// baseline (speedup 1.0000x reference)
#include <cuda_runtime.h>
#include <cuda_bf16.h>
#include <cuda_fp16.h>
#include <cstdint>

// Problem constants
constexpr int CDIM  = 384;
constexpr int NHEAD = 12;
constexpr int DHEAD = 32;
constexpr int NB    = 16;
constexpr int NN    = 1024;            // 32*32 tokens
constexpr int MT    = NB * NN;         // 16384 rows
constexpr float QK_SCALE = 0.17677669529663687f; // 32^-0.5
constexpr float LOG2E    = 1.4426950408889634f;
constexpr float QS2      = QK_SCALE * LOG2E;     // folded into K at qkv epilogue

// Scratch (static device globals; no runtime allocation)
__device__ float  g_q [(size_t)NB * NHEAD * NN * DHEAD];  // fp32 Q
__device__ __half g_k [(size_t)NB * NHEAD * NN * DHEAD];  // fp16 K (pre-scaled)
__device__ __half g_v [(size_t)NB * NHEAD * NN * DHEAD];  // fp16 V
__device__ __half g_x [(size_t)MT * CDIM];        // x transposed [m][k], fp16
__device__ __half g_wh[(size_t)3 * CDIM * CDIM];  // qkv_w [o][k] fp16 hi
__device__ __half g_wl[(size_t)3 * CDIM * CDIM];  // qkv_w fp16 lo
__device__ __half g_pwh[(size_t)CDIM * CDIM];     // proj_w fp16 hi
__device__ __half g_pwl[(size_t)CDIM * CDIM];     // proj_w fp16 lo
__device__ __half g_ao[(size_t)MT * CDIM];        // attention out [m][c], fp16

// ===========================================================================
// Helpers
// ===========================================================================
__device__ __forceinline__ float ex2f(float x) {
    float y; asm("ex2.approx.ftz.f32 %0, %1;" : "=f"(y) : "f"(x)); return y;
}
// fp16 hi/lo split
__device__ __forceinline__ void split1h(float a, __half& h, __half& l) {
    h = __float2half_rn(a);
    l = __float2half_rn(a - __half2float(h));
}
__device__ __forceinline__ uint32_t pack_h2(float a, float b) {
    __half2 h = __floats2half2_rn(a, b);
    return *(uint32_t*)&h;
}
__device__ __forceinline__ uint32_t smem_u32(const void* p) {
    uint32_t a;
    asm("{ .reg .u64 t; cvta.to.shared.u64 t, %1; cvt.u32.u64 %0, t; }"
        : "=r"(a) : "l"(p));
    return a;
}
#define LDMX2(r0, r1, addr) \
    asm volatile("ldmatrix.sync.aligned.m8n8.x2.shared.b16 {%0,%1}, [%2];" \
                 : "=r"(r0), "=r"(r1) : "r"(addr))
#define LDMX2T(r0, r1, addr) \
    asm volatile("ldmatrix.sync.aligned.m8n8.x2.trans.shared.b16 {%0,%1}, [%2];" \
                 : "=r"(r0), "=r"(r1) : "r"(addr))
#define LDMX4(r, addr) \
    asm volatile("ldmatrix.sync.aligned.m8n8.x4.shared.b16 {%0,%1,%2,%3}, [%4];" \
                 : "=r"((r)[0]), "=r"((r)[1]), "=r"((r)[2]), "=r"((r)[3]) : "r"(addr))
__device__ __forceinline__ void mma_f16(float* d, const uint32_t* a,
                                        uint32_t b0, uint32_t b1) {
    asm volatile(
        "mma.sync.aligned.m16n8k16.row.col.f32.f16.f16.f32 "
        "{%0,%1,%2,%3}, {%4,%5,%6,%7}, {%8,%9}, {%0,%1,%2,%3};"
        : "+f"(d[0]), "+f"(d[1]), "+f"(d[2]), "+f"(d[3])
        : "r"(a[0]), "r"(a[1]), "r"(a[2]), "r"(a[3]), "r"(b0), "r"(b1));
}
#define CP_ASYNC16(saddr, gptr) \
    asm volatile("cp.async.ca.shared.global [%0], [%1], 16;" \
                 :: "r"(saddr), "l"(gptr) : "memory")
#define CP_COMMIT() asm volatile("cp.async.commit_group;" ::: "memory")
#define CP_WAIT(n)  asm volatile("cp.async.wait_group %0;" :: "n"(n) : "memory")

// ---------------------------------------------------------------------------
// Kernel 0a: transpose x [b,c,n] fp32 -> g_x [m=b*NN+n][k=c] fp16 single
// ---------------------------------------------------------------------------
__global__ __launch_bounds__(256) void convert_x(const float* __restrict__ x) {
    __shared__ float tile[32][33];
    const int b  = blockIdx.z;
    const int n0 = blockIdx.x * 32;
    const int c0 = blockIdx.y * 32;
    const int tx = threadIdx.x, ty = threadIdx.y;   // (32, 8)
    #pragma unroll
    for (int j = 0; j < 4; j++) {
        int c = c0 + ty + j * 8;
        tile[ty + j * 8][tx] = x[((size_t)b * CDIM + c) * NN + n0 + tx];
    }
    __syncthreads();
    #pragma unroll
    for (int j = 0; j < 4; j++) {
        int n = n0 + ty + j * 8;
        size_t idx = ((size_t)b * NN + n) * CDIM + c0 + tx;
        g_x[idx] = __float2half_rn(tile[tx][ty + j * 8]);
    }
}

// ---------------------------------------------------------------------------
// Kernel 0b: split weights (qkv_w and proj_w) into fp16 hi/lo.
// ---------------------------------------------------------------------------
__global__ __launch_bounds__(256) void convert_w(const float* __restrict__ qkv_w,
                                                 const float* __restrict__ proj_w) {
    const int i = blockIdx.x * 256 + threadIdx.x;
    const int NW = 3 * CDIM * CDIM;
    if (i < NW) {
        __half h, l; split1h(qkv_w[i], h, l);
        g_wh[i] = h; g_wl[i] = l;
    }
    if (i < CDIM * CDIM) {
        __half h, l; split1h(proj_w[i], h, l);
        g_pwh[i] = h; g_pwl[i] = l;
    }
}

// ---------------------------------------------------------------------------
// Kernel 1: QKV GEMM, fp16 2-term mma.sync: C = x_f16 . (wh + wl).
// Tile 256m x 128o, 512 threads (16 warps, warp tile 64m x 32o), k-step 32.
// Epilogue: Q fp32; K fp16 single scaled by QS2; V fp16 single.
// ---------------------------------------------------------------------------
constexpr int GROWB = 80;   // 32 elems * 2B = 64B data + 16B pad

__global__ __launch_bounds__(512) void qkv_mma() {
    __shared__ __align__(16) char sA [256 * GROWB];
    __shared__ __align__(16) char sBh[128 * GROWB], sBl[128 * GROWB];

    const int tid  = threadIdx.x;
    const int w    = tid >> 5, lane = tid & 31;
    const int mw   = w & 3,   ow   = w >> 2;      // 4 m-warps x 4 o-warps
    const int m0   = blockIdx.x * 256;
    const int o0   = blockIdx.y * 128;
    const int b    = m0 >> 10;

    const uint32_t a_s  = smem_u32(sA);
    const uint32_t bh_s = smem_u32(sBh), bl_s = smem_u32(sBl);

    float acc[4][4][4];
    #pragma unroll
    for (int mt = 0; mt < 4; mt++)
        #pragma unroll
        for (int nt = 0; nt < 4; nt++)
            #pragma unroll
            for (int e = 0; e < 4; e++) acc[mt][nt][e] = 0.f;

    for (int it = 0; it < CDIM / 32; it++) {
        const int k0 = it * 32;
        __syncthreads();
        // A tile: 256 rows x 4 c4-slots = 1024 slots, 2 passes of 512
        #pragma unroll
        for (int r = 0; r < 2; r++) {
            int idx = tid + 512 * r;
            int row = idx >> 2, c4 = idx & 3;
            size_t ga = (size_t)(m0 + row) * CDIM + k0 + c4 * 8;
            *(uint4*)(sA + row * GROWB + c4 * 16) = *(const uint4*)(g_x + ga);
        }
        // B tiles: 128 rows x 4 slots = 512 slots, 1 pass each
        {
            int row = tid >> 2, c4 = tid & 3;
            size_t gb = (size_t)(o0 + row) * CDIM + k0 + c4 * 8;
            *(uint4*)(sBh + row * GROWB + c4 * 16) = *(const uint4*)(g_wh + gb);
            *(uint4*)(sBl + row * GROWB + c4 * 16) = *(const uint4*)(g_wl + gb);
        }
        __syncthreads();

        #pragma unroll
        for (int ks = 0; ks < 2; ks++) {
            uint32_t ah[4][4];
            const uint32_t aoff = (uint32_t)((mw * 64 + (lane & 15)) * GROWB
                                             + (ks * 16 + (lane >> 4) * 8) * 2);
            #pragma unroll
            for (int mt = 0; mt < 4; mt++)
                LDMX4(ah[mt], a_s + aoff + mt * 16 * GROWB);
            const uint32_t boff = (uint32_t)((ow * 32 + (lane & 7)) * GROWB
                                             + (ks * 16 + ((lane >> 3) & 1) * 8) * 2);
            #pragma unroll
            for (int nt = 0; nt < 4; nt++) {
                uint32_t b0, b1, c0r, c1;
                LDMX2(b0, b1, bh_s + boff + nt * 8 * GROWB);
                LDMX2(c0r, c1, bl_s + boff + nt * 8 * GROWB);
                #pragma unroll
                for (int mt = 0; mt < 4; mt++) {
                    mma_f16(acc[mt][nt], ah[mt], b0, b1);
                    mma_f16(acc[mt][nt], ah[mt], c0r, c1);
                }
            }
        }
    }

    // Epilogue: Q -> fp32; K -> fp16 (scaled by QS2); V -> fp16 single.
    const int g = lane >> 2, t4 = lane & 3;
    #pragma unroll
    for (int mt = 0; mt < 4; mt++) {
        const int n = (m0 + mw * 64 + mt * 16 + g) & (NN - 1);
        #pragma unroll
        for (int nt = 0; nt < 4; nt++) {
            const int o   = o0 + ow * 32 + nt * 8 + t4 * 2;
            const int wch = o / CDIM;
            const int rem = o % CDIM;
            const int h   = rem >> 5, d = rem & 31;
            const size_t base0 = ((size_t)(b * NHEAD + h) * NN + n) * DHEAD + d;
            const size_t base1 = base0 + 8 * DHEAD;   // row n+8
            float* ac = acc[mt][nt];
            if (wch == 0) {
                *(float2*)(g_q + base0) = make_float2(ac[0], ac[1]);
                *(float2*)(g_q + base1) = make_float2(ac[2], ac[3]);
            } else if (wch == 1) {
                *(uint32_t*)(g_k + base0) = pack_h2(ac[0] * QS2, ac[1] * QS2);
                *(uint32_t*)(g_k + base1) = pack_h2(ac[2] * QS2, ac[3] * QS2);
            } else {
                *(uint32_t*)(g_v + base0) = pack_h2(ac[0], ac[1]);
                *(uint32_t*)(g_v + base1) = pack_h2(ac[2], ac[3]);
            }
        }
    }
}

// ---------------------------------------------------------------------------
// Kernel 2: flash attention, fp16 mma.sync single-term (verified R14/R15):
//   S = q_fp16 . k_fp16; P = fp16(exp2(S)); O += P . v_fp16
// ---------------------------------------------------------------------------
constexpr int ROWB = 80;

__global__ __launch_bounds__(128, 4) void attn_mma() {
    __shared__ __align__(16) char sk[2][64 * ROWB];
    __shared__ __align__(16) char sv[2][64 * ROWB];

    const int tid = threadIdx.x;
    const int w   = tid >> 5;
    const int l   = tid & 31;
    const int g   = l >> 2;
    const int t4  = l & 3;
    const int lane = l & 15;
    const int bh  = blockIdx.y;
    const int n0  = blockIdx.x * 128;

    const uint32_t sk0 = smem_u32(sk[0]);
    const uint32_t sv0 = smem_u32(sv[0]);
    constexpr uint32_t BUFB = 64 * ROWB;

    // ---- per-thread chunk-load geometry ----
    const int    ldrow = tid >> 2, ldc4 = tid & 3;
    const size_t ldsrc0 = ((size_t)bh * NN + ldrow) * DHEAD + ldc4 * 8;
    const uint32_t lddst = (uint32_t)(ldrow * ROWB + ldc4 * 16);
    const size_t ldsrc1 = ldsrc0 + (size_t)32 * DHEAD;
    const uint32_t lddst1 = lddst + 32 * ROWB;

    // ---- prologue: async-load chunk 0 into buffer 0 ----
    CP_ASYNC16(sk0 + lddst,  g_k + ldsrc0);
    CP_ASYNC16(sk0 + lddst1, g_k + ldsrc1);
    CP_ASYNC16(sv0 + lddst,  g_v + ldsrc0);
    CP_ASYNC16(sv0 + lddst1, g_v + ldsrc1);
    CP_COMMIT();

    // ---- Q fragments: single fp16 (no scale; folded into K) ----
    uint32_t qh[2][2][4];
    {
        const float* qb = g_q + ((size_t)bh * NN + n0 + w * 32) * DHEAD;
        #pragma unroll
        for (int mt = 0; mt < 2; mt++)
            #pragma unroll
            for (int ks = 0; ks < 2; ks++) {
                int rA = mt * 16 + g, rB = rA + 8, kk = ks * 16 + t4 * 2;
                float2 v0 = *(const float2*)(qb + rA * DHEAD + kk);
                float2 v1 = *(const float2*)(qb + rB * DHEAD + kk);
                float2 v2 = *(const float2*)(qb + rA * DHEAD + kk + 8);
                float2 v3 = *(const float2*)(qb + rB * DHEAD + kk + 8);
                qh[mt][ks][0] = pack_h2(v0.x, v0.y);
                qh[mt][ks][1] = pack_h2(v1.x, v1.y);
                qh[mt][ks][2] = pack_h2(v2.x, v2.y);
                qh[mt][ks][3] = pack_h2(v3.x, v3.y);
            }
    }

    float of[2][4][4];
    #pragma unroll
    for (int mt = 0; mt < 2; mt++)
        #pragma unroll
        for (int nt = 0; nt < 4; nt++)
            #pragma unroll
            for (int e = 0; e < 4; e++) of[mt][nt][e] = 0.f;

    float lA[2] = {0.f, 0.f}, lB[2] = {0.f, 0.f};

    for (int it = 0; it < 16; it++) {
        const uint32_t bofs = (uint32_t)(it & 1) * BUFB;
        if (it < 15) {
            const uint32_t nofs = (uint32_t)((it + 1) & 1) * BUFB;
            const size_t koff = (size_t)(it + 1) * 64 * DHEAD;
            CP_ASYNC16(sk0 + nofs + lddst,  g_k + ldsrc0 + koff);
            CP_ASYNC16(sk0 + nofs + lddst1, g_k + ldsrc1 + koff);
            CP_ASYNC16(sv0 + nofs + lddst,  g_v + ldsrc0 + koff);
            CP_ASYNC16(sv0 + nofs + lddst1, g_v + ldsrc1 + koff);
            CP_COMMIT();
            CP_WAIT(1);
        } else {
            CP_WAIT(0);
        }
        __syncthreads();

        // ---- interleaved: per 16-key group: S-mma -> exp -> pack -> PV ----
        #pragma unroll
        for (int s = 0; s < 4; s++) {
            uint32_t pfh[2][4];
            #pragma unroll
            for (int hhf = 0; hhf < 2; hhf++) {
                const int nt = 2 * s + hhf;
                float sf[2][4];
                #pragma unroll
                for (int mt = 0; mt < 2; mt++)
                    #pragma unroll
                    for (int e = 0; e < 4; e++) sf[mt][e] = 0.f;
                #pragma unroll
                for (int ks = 0; ks < 2; ks++) {
                    uint32_t aoff = bofs + (uint32_t)((nt * 8 + (lane & 7)) * ROWB
                                               + (ks * 16 + (lane >> 3) * 8) * 2);
                    uint32_t k0f, k1f;
                    LDMX2(k0f, k1f, sk0 + aoff);
                    #pragma unroll
                    for (int mt = 0; mt < 2; mt++)
                        mma_f16(sf[mt], qh[mt][ks], k0f, k1f);
                }
                #pragma unroll
                for (int mt = 0; mt < 2; mt++) {
                    float p0 = ex2f(sf[mt][0]);
                    float p1 = ex2f(sf[mt][1]);
                    float p2 = ex2f(sf[mt][2]);
                    float p3 = ex2f(sf[mt][3]);
                    lA[mt] += p0 + p1;
                    lB[mt] += p2 + p3;
                    pfh[mt][hhf * 2]     = pack_h2(p0, p1);
                    pfh[mt][hhf * 2 + 1] = pack_h2(p2, p3);
                }
            }
            // ---- O += P.v for keys [s*16, s*16+16) ----
            #pragma unroll
            for (int nt = 0; nt < 4; nt++) {
                uint32_t voff = bofs + (uint32_t)((s * 16 + lane) * ROWB + nt * 16);
                uint32_t v0f, v1f;
                LDMX2T(v0f, v1f, sv0 + voff);
                #pragma unroll
                for (int mt = 0; mt < 2; mt++)
                    mma_f16(of[mt][nt], pfh[mt], v0f, v1f);
            }
        }
        __syncthreads();
    }

    // ---- normalize + write g_ao [m][c] fp16 single (proj A-side) ----
    const int bb = bh / NHEAD, hh = bh % NHEAD;
    #pragma unroll
    for (int mt = 0; mt < 2; mt++) {
        float a = lA[mt], b2 = lB[mt];
        a  += __shfl_xor_sync(0xffffffffu, a, 1);
        a  += __shfl_xor_sync(0xffffffffu, a, 2);
        b2 += __shfl_xor_sync(0xffffffffu, b2, 1);
        b2 += __shfl_xor_sync(0xffffffffu, b2, 2);
        const float ia = 1.f / a, ib = 1.f / b2;
        const int rA = n0 + w * 32 + mt * 16 + g;
        const size_t baseA = ((size_t)(bb * NN) + rA) * CDIM + hh * DHEAD;
        const size_t baseB = baseA + (size_t)8 * CDIM;
        #pragma unroll
        for (int nt = 0; nt < 4; nt++) {
            int col = nt * 8 + t4 * 2;
            *(uint32_t*)(g_ao + baseA + col) =
                pack_h2(of[mt][nt][0] * ia, of[mt][nt][1] * ia);
            *(uint32_t*)(g_ao + baseB + col) =
                pack_h2(of[mt][nt][2] * ib, of[mt][nt][3] * ib);
        }
    }
}

// ---------------------------------------------------------------------------
// Kernel 3: projection GEMM, fp16 2-term: out = ao_f16 . (pwh + pwl) + bias.
// Tile 256m x 128o, 512 threads.
// ---------------------------------------------------------------------------
__global__ __launch_bounds__(512) void proj_mma(const float* __restrict__ bias,
                                                float* __restrict__ out) {
    __shared__ __align__(16) char sA [256 * GROWB];
    __shared__ __align__(16) char sBh[128 * GROWB], sBl[128 * GROWB];

    const int tid  = threadIdx.x;
    const int w    = tid >> 5, lane = tid & 31;
    const int mw   = w & 3,   ow   = w >> 2;
    const int m0   = blockIdx.x * 256;
    const int o0   = blockIdx.y * 128;
    const int b    = m0 >> 10;

    const uint32_t a_s  = smem_u32(sA);
    const uint32_t bh_s = smem_u32(sBh), bl_s = smem_u32(sBl);

    float acc[4][4][4];
    #pragma unroll
    for (int mt = 0; mt < 4; mt++)
        #pragma unroll
        for (int nt = 0; nt < 4; nt++)
            #pragma unroll
            for (int e = 0; e < 4; e++) acc[mt][nt][e] = 0.f;

    for (int it = 0; it < CDIM / 32; it++) {
        const int k0 = it * 32;
        __syncthreads();
        #pragma unroll
        for (int r = 0; r < 2; r++) {
            int idx = tid + 512 * r;
            int row = idx >> 2, c4 = idx & 3;
            size_t ga = (size_t)(m0 + row) * CDIM + k0 + c4 * 8;
            *(uint4*)(sA + row * GROWB + c4 * 16) = *(const uint4*)(g_ao + ga);
        }
        {
            int row = tid >> 2, c4 = tid & 3;
            size_t gb = (size_t)(o0 + row) * CDIM + k0 + c4 * 8;
            *(uint4*)(sBh + row * GROWB + c4 * 16) = *(const uint4*)(g_pwh + gb);
            *(uint4*)(sBl + row * GROWB + c4 * 16) = *(const uint4*)(g_pwl + gb);
        }
        __syncthreads();

        #pragma unroll
        for (int ks = 0; ks < 2; ks++) {
            uint32_t ah[4][4];
            const uint32_t aoff = (uint32_t)((mw * 64 + (lane & 15)) * GROWB
                                             + (ks * 16 + (lane >> 4) * 8) * 2);
            #pragma unroll
            for (int mt = 0; mt < 4; mt++)
                LDMX4(ah[mt], a_s + aoff + mt * 16 * GROWB);
            const uint32_t boff = (uint32_t)((ow * 32 + (lane & 7)) * GROWB
                                             + (ks * 16 + ((lane >> 3) & 1) * 8) * 2);
            #pragma unroll
            for (int nt = 0; nt < 4; nt++) {
                uint32_t b0, b1, c0r, c1;
                LDMX2(b0, b1, bh_s + boff + nt * 8 * GROWB);
                LDMX2(c0r, c1, bl_s + boff + nt * 8 * GROWB);
                #pragma unroll
                for (int mt = 0; mt < 4; mt++) {
                    mma_f16(acc[mt][nt], ah[mt], b0, b1);
                    mma_f16(acc[mt][nt], ah[mt], c0r, c1);
                }
            }
        }
    }

    // Epilogue: out[b][o][n] = acc + bias[o]
    const int g = lane >> 2, t4 = lane & 3;
    #pragma unroll
    for (int nt = 0; nt < 4; nt++) {
        const int o = o0 + ow * 32 + nt * 8 + t4 * 2;
        const float b0v = bias[o], b1v = bias[o + 1];
        float* r0 = out + ((size_t)b * CDIM + o) * NN;
        float* r1 = r0 + NN;
        #pragma unroll
        for (int mt = 0; mt < 4; mt++) {
            const int n = (m0 + mw * 64 + mt * 16 + g) & (NN - 1);
            float* ac = acc[mt][nt];
            r0[n]     = ac[0] + b0v;
            r1[n]     = ac[1] + b1v;
            r0[n + 8] = ac[2] + b0v;
            r1[n + 8] = ac[3] + b1v;
        }
    }
}

// ---------------------------------------------------------------------------
extern "C" void kernel_launch(void* const* d_in, const int* in_sizes, int n_in,
                              void* d_out, int out_size) {
    const float* x      = (const float*)d_in[0];   // [16,384,32,32]
    const float* qkv_w  = (const float*)d_in[1];   // [1152,384]
    const float* proj_w = (const float*)d_in[2];   // [384,384]
    const float* proj_b = (const float*)d_in[3];   // [384]
    float* out = (float*)d_out;                    // [16,384,32,32]

    convert_x<<<dim3(NN / 32, CDIM / 32, NB), dim3(32, 8)>>>(x);
    convert_w<<<(3 * CDIM * CDIM + 255) / 256, 256>>>(qkv_w, proj_w);
    qkv_mma<<<dim3(MT / 256, (3 * CDIM) / 128), 512>>>();
    attn_mma<<<dim3(NN / 128, NB * NHEAD), 128>>>();
    proj_mma<<<dim3(MT / 256, CDIM / 128), 512>>>(proj_b, out);
}

// round 17
// speedup vs baseline: 1.0231x; 1.0231x over previous
#include <cuda_runtime.h>
#include <cuda_bf16.h>
#include <cuda_fp16.h>
#include <cstdint>

// Problem constants
constexpr int CDIM  = 384;
constexpr int NHEAD = 12;
constexpr int DHEAD = 32;
constexpr int NB    = 16;
constexpr int NN    = 1024;            // 32*32 tokens
constexpr int MT    = NB * NN;         // 16384 rows
constexpr float QK_SCALE = 0.17677669529663687f; // 32^-0.5
constexpr float LOG2E    = 1.4426950408889634f;
constexpr float QS2      = QK_SCALE * LOG2E;     // folded into K at qkv epilogue

// Scratch (static device globals; no runtime allocation)
__device__ __half g_q [(size_t)NB * NHEAD * NN * DHEAD];  // fp16 Q
__device__ __half g_k [(size_t)NB * NHEAD * NN * DHEAD];  // fp16 K (pre-scaled)
__device__ __half g_v [(size_t)NB * NHEAD * NN * DHEAD];  // fp16 V
__device__ __half g_x [(size_t)MT * CDIM];        // x transposed [m][k], fp16
__device__ __half g_wh[(size_t)3 * CDIM * CDIM];  // qkv_w [o][k] fp16 hi
__device__ __half g_wl[(size_t)3 * CDIM * CDIM];  // qkv_w fp16 lo
__device__ __half g_pwh[(size_t)CDIM * CDIM];     // proj_w fp16 hi
__device__ __half g_pwl[(size_t)CDIM * CDIM];     // proj_w fp16 lo
__device__ __half g_ao[(size_t)MT * CDIM];        // attention out [m][c], fp16

// ===========================================================================
// Helpers
// ===========================================================================
__device__ __forceinline__ float ex2f(float x) {
    float y; asm("ex2.approx.ftz.f32 %0, %1;" : "=f"(y) : "f"(x)); return y;
}
// fp16 hi/lo split
__device__ __forceinline__ void split1h(float a, __half& h, __half& l) {
    h = __float2half_rn(a);
    l = __float2half_rn(a - __half2float(h));
}
__device__ __forceinline__ uint32_t pack_h2(float a, float b) {
    __half2 h = __floats2half2_rn(a, b);
    return *(uint32_t*)&h;
}
__device__ __forceinline__ uint32_t smem_u32(const void* p) {
    uint32_t a;
    asm("{ .reg .u64 t; cvta.to.shared.u64 t, %1; cvt.u32.u64 %0, t; }"
        : "=r"(a) : "l"(p));
    return a;
}
#define LDMX2(r0, r1, addr) \
    asm volatile("ldmatrix.sync.aligned.m8n8.x2.shared.b16 {%0,%1}, [%2];" \
                 : "=r"(r0), "=r"(r1) : "r"(addr))
#define LDMX2T(r0, r1, addr) \
    asm volatile("ldmatrix.sync.aligned.m8n8.x2.trans.shared.b16 {%0,%1}, [%2];" \
                 : "=r"(r0), "=r"(r1) : "r"(addr))
#define LDMX4(r, addr) \
    asm volatile("ldmatrix.sync.aligned.m8n8.x4.shared.b16 {%0,%1,%2,%3}, [%4];" \
                 : "=r"((r)[0]), "=r"((r)[1]), "=r"((r)[2]), "=r"((r)[3]) : "r"(addr))
__device__ __forceinline__ void mma_f16(float* d, const uint32_t* a,
                                        uint32_t b0, uint32_t b1) {
    asm volatile(
        "mma.sync.aligned.m16n8k16.row.col.f32.f16.f16.f32 "
        "{%0,%1,%2,%3}, {%4,%5,%6,%7}, {%8,%9}, {%0,%1,%2,%3};"
        : "+f"(d[0]), "+f"(d[1]), "+f"(d[2]), "+f"(d[3])
        : "r"(a[0]), "r"(a[1]), "r"(a[2]), "r"(a[3]), "r"(b0), "r"(b1));
}
#define CP_ASYNC16(saddr, gptr) \
    asm volatile("cp.async.ca.shared.global [%0], [%1], 16;" \
                 :: "r"(saddr), "l"(gptr) : "memory")
#define CP_COMMIT() asm volatile("cp.async.commit_group;" ::: "memory")
#define CP_WAIT(n)  asm volatile("cp.async.wait_group %0;" :: "n"(n) : "memory")

// ---------------------------------------------------------------------------
// Kernel 0a: transpose x [b,c,n] fp32 -> g_x [m=b*NN+n][k=c] fp16 single
// ---------------------------------------------------------------------------
__global__ __launch_bounds__(256) void convert_x(const float* __restrict__ x) {
    __shared__ float tile[32][33];
    const int b  = blockIdx.z;
    const int n0 = blockIdx.x * 32;
    const int c0 = blockIdx.y * 32;
    const int tx = threadIdx.x, ty = threadIdx.y;   // (32, 8)
    #pragma unroll
    for (int j = 0; j < 4; j++) {
        int c = c0 + ty + j * 8;
        tile[ty + j * 8][tx] = x[((size_t)b * CDIM + c) * NN + n0 + tx];
    }
    __syncthreads();
    #pragma unroll
    for (int j = 0; j < 4; j++) {
        int n = n0 + ty + j * 8;
        size_t idx = ((size_t)b * NN + n) * CDIM + c0 + tx;
        g_x[idx] = __float2half_rn(tile[tx][ty + j * 8]);
    }
}

// ---------------------------------------------------------------------------
// Kernel 0b: split weights (qkv_w and proj_w) into fp16 hi/lo.
// ---------------------------------------------------------------------------
__global__ __launch_bounds__(256) void convert_w(const float* __restrict__ qkv_w,
                                                 const float* __restrict__ proj_w) {
    const int i = blockIdx.x * 256 + threadIdx.x;
    const int NW = 3 * CDIM * CDIM;
    if (i < NW) {
        __half h, l; split1h(qkv_w[i], h, l);
        g_wh[i] = h; g_wl[i] = l;
    }
    if (i < CDIM * CDIM) {
        __half h, l; split1h(proj_w[i], h, l);
        g_pwh[i] = h; g_pwl[i] = l;
    }
}

// ---------------------------------------------------------------------------
// Kernel 1: QKV GEMM, fp16 2-term mma.sync: C = x_f16 . (wh + wl).
// Tile 128m x 128o, 256 threads (R15 verified config), k-step 32.
// Epilogue: Q fp16; K fp16 scaled by QS2; V fp16 — all packed uint32 stores.
// ---------------------------------------------------------------------------
constexpr int GROWB = 80;   // 32 elems * 2B = 64B data + 16B pad

__global__ __launch_bounds__(256) void qkv_mma() {
    __shared__ __align__(16) char sA [128 * GROWB];
    __shared__ __align__(16) char sBh[128 * GROWB], sBl[128 * GROWB];

    const int tid  = threadIdx.x;
    const int w    = tid >> 5, lane = tid & 31;
    const int mw   = w & 1,   ow   = w >> 1;      // warp tile: 64m x 32o
    const int m0   = blockIdx.x * 128;
    const int o0   = blockIdx.y * 128;
    const int b    = m0 >> 10;

    const uint32_t a_s  = smem_u32(sA);
    const uint32_t bh_s = smem_u32(sBh), bl_s = smem_u32(sBl);

    float acc[4][4][4];
    #pragma unroll
    for (int mt = 0; mt < 4; mt++)
        #pragma unroll
        for (int nt = 0; nt < 4; nt++)
            #pragma unroll
            for (int e = 0; e < 4; e++) acc[mt][nt][e] = 0.f;

    for (int it = 0; it < CDIM / 32; it++) {
        const int k0 = it * 32;
        __syncthreads();
        #pragma unroll
        for (int r = 0; r < 2; r++) {
            int idx = tid + 256 * r;
            int row = idx >> 2, c4 = idx & 3;
            size_t ga = (size_t)(m0 + row) * CDIM + k0 + c4 * 8;
            size_t gb = (size_t)(o0 + row) * CDIM + k0 + c4 * 8;
            *(uint4*)(sA  + row * GROWB + c4 * 16) = *(const uint4*)(g_x  + ga);
            *(uint4*)(sBh + row * GROWB + c4 * 16) = *(const uint4*)(g_wh + gb);
            *(uint4*)(sBl + row * GROWB + c4 * 16) = *(const uint4*)(g_wl + gb);
        }
        __syncthreads();

        #pragma unroll
        for (int ks = 0; ks < 2; ks++) {
            uint32_t ah[4][4];
            const uint32_t aoff = (uint32_t)((mw * 64 + (lane & 15)) * GROWB
                                             + (ks * 16 + (lane >> 4) * 8) * 2);
            #pragma unroll
            for (int mt = 0; mt < 4; mt++)
                LDMX4(ah[mt], a_s + aoff + mt * 16 * GROWB);
            const uint32_t boff = (uint32_t)((ow * 32 + (lane & 7)) * GROWB
                                             + (ks * 16 + ((lane >> 3) & 1) * 8) * 2);
            #pragma unroll
            for (int nt = 0; nt < 4; nt++) {
                uint32_t b0, b1, c0r, c1;
                LDMX2(b0, b1, bh_s + boff + nt * 8 * GROWB);
                LDMX2(c0r, c1, bl_s + boff + nt * 8 * GROWB);
                #pragma unroll
                for (int mt = 0; mt < 4; mt++) {
                    mma_f16(acc[mt][nt], ah[mt], b0, b1);
                    mma_f16(acc[mt][nt], ah[mt], c0r, c1);
                }
            }
        }
    }

    // Epilogue: Q fp16; K fp16 (scaled by QS2); V fp16. Uniform packed stores.
    const int g = lane >> 2, t4 = lane & 3;
    #pragma unroll
    for (int mt = 0; mt < 4; mt++) {
        const int n = (m0 + mw * 64 + mt * 16 + g) & (NN - 1);
        #pragma unroll
        for (int nt = 0; nt < 4; nt++) {
            const int o   = o0 + ow * 32 + nt * 8 + t4 * 2;
            const int wch = o / CDIM;
            const int rem = o % CDIM;
            const int h   = rem >> 5, d = rem & 31;
            const size_t base0 = ((size_t)(b * NHEAD + h) * NN + n) * DHEAD + d;
            const size_t base1 = base0 + 8 * DHEAD;   // row n+8
            float* ac = acc[mt][nt];
            const float s = (wch == 1) ? QS2 : 1.0f;
            __half* dst = (wch == 0) ? g_q : (wch == 1) ? g_k : g_v;
            *(uint32_t*)(dst + base0) = pack_h2(ac[0] * s, ac[1] * s);
            *(uint32_t*)(dst + base1) = pack_h2(ac[2] * s, ac[3] * s);
        }
    }
}

// ---------------------------------------------------------------------------
// Kernel 2: flash attention, fp16 mma.sync single-term (verified R14/R15):
//   S = q_fp16 . k_fp16; P = fp16(exp2(S)); O += P . v_fp16
// Q now loaded directly as packed fp16 (no conversion).
// ---------------------------------------------------------------------------
constexpr int ROWB = 80;

__global__ __launch_bounds__(128, 4) void attn_mma() {
    __shared__ __align__(16) char sk[2][64 * ROWB];
    __shared__ __align__(16) char sv[2][64 * ROWB];

    const int tid = threadIdx.x;
    const int w   = tid >> 5;
    const int l   = tid & 31;
    const int g   = l >> 2;
    const int t4  = l & 3;
    const int lane = l & 15;
    const int bh  = blockIdx.y;
    const int n0  = blockIdx.x * 128;

    const uint32_t sk0 = smem_u32(sk[0]);
    const uint32_t sv0 = smem_u32(sv[0]);
    constexpr uint32_t BUFB = 64 * ROWB;

    // ---- per-thread chunk-load geometry ----
    const int    ldrow = tid >> 2, ldc4 = tid & 3;
    const size_t ldsrc0 = ((size_t)bh * NN + ldrow) * DHEAD + ldc4 * 8;
    const uint32_t lddst = (uint32_t)(ldrow * ROWB + ldc4 * 16);
    const size_t ldsrc1 = ldsrc0 + (size_t)32 * DHEAD;
    const uint32_t lddst1 = lddst + 32 * ROWB;

    // ---- prologue: async-load chunk 0 into buffer 0 ----
    CP_ASYNC16(sk0 + lddst,  g_k + ldsrc0);
    CP_ASYNC16(sk0 + lddst1, g_k + ldsrc1);
    CP_ASYNC16(sv0 + lddst,  g_v + ldsrc0);
    CP_ASYNC16(sv0 + lddst1, g_v + ldsrc1);
    CP_COMMIT();

    // ---- Q fragments: direct packed fp16 loads ----
    uint32_t qh[2][2][4];
    {
        const __half* qb = g_q + ((size_t)bh * NN + n0 + w * 32) * DHEAD;
        #pragma unroll
        for (int mt = 0; mt < 2; mt++)
            #pragma unroll
            for (int ks = 0; ks < 2; ks++) {
                int rA = mt * 16 + g, rB = rA + 8, kk = ks * 16 + t4 * 2;
                qh[mt][ks][0] = *(const uint32_t*)(qb + rA * DHEAD + kk);
                qh[mt][ks][1] = *(const uint32_t*)(qb + rB * DHEAD + kk);
                qh[mt][ks][2] = *(const uint32_t*)(qb + rA * DHEAD + kk + 8);
                qh[mt][ks][3] = *(const uint32_t*)(qb + rB * DHEAD + kk + 8);
            }
    }

    float of[2][4][4];
    #pragma unroll
    for (int mt = 0; mt < 2; mt++)
        #pragma unroll
        for (int nt = 0; nt < 4; nt++)
            #pragma unroll
            for (int e = 0; e < 4; e++) of[mt][nt][e] = 0.f;

    float lA[2] = {0.f, 0.f}, lB[2] = {0.f, 0.f};

    for (int it = 0; it < 16; it++) {
        const uint32_t bofs = (uint32_t)(it & 1) * BUFB;
        if (it < 15) {
            const uint32_t nofs = (uint32_t)((it + 1) & 1) * BUFB;
            const size_t koff = (size_t)(it + 1) * 64 * DHEAD;
            CP_ASYNC16(sk0 + nofs + lddst,  g_k + ldsrc0 + koff);
            CP_ASYNC16(sk0 + nofs + lddst1, g_k + ldsrc1 + koff);
            CP_ASYNC16(sv0 + nofs + lddst,  g_v + ldsrc0 + koff);
            CP_ASYNC16(sv0 + nofs + lddst1, g_v + ldsrc1 + koff);
            CP_COMMIT();
            CP_WAIT(1);
        } else {
            CP_WAIT(0);
        }
        __syncthreads();

        // ---- interleaved: per 16-key group: S-mma -> exp -> pack -> PV ----
        #pragma unroll
        for (int s = 0; s < 4; s++) {
            uint32_t pfh[2][4];
            #pragma unroll
            for (int hhf = 0; hhf < 2; hhf++) {
                const int nt = 2 * s + hhf;
                float sf[2][4];
                #pragma unroll
                for (int mt = 0; mt < 2; mt++)
                    #pragma unroll
                    for (int e = 0; e < 4; e++) sf[mt][e] = 0.f;
                #pragma unroll
                for (int ks = 0; ks < 2; ks++) {
                    uint32_t aoff = bofs + (uint32_t)((nt * 8 + (lane & 7)) * ROWB
                                               + (ks * 16 + (lane >> 3) * 8) * 2);
                    uint32_t k0f, k1f;
                    LDMX2(k0f, k1f, sk0 + aoff);
                    #pragma unroll
                    for (int mt = 0; mt < 2; mt++)
                        mma_f16(sf[mt], qh[mt][ks], k0f, k1f);
                }
                #pragma unroll
                for (int mt = 0; mt < 2; mt++) {
                    float p0 = ex2f(sf[mt][0]);
                    float p1 = ex2f(sf[mt][1]);
                    float p2 = ex2f(sf[mt][2]);
                    float p3 = ex2f(sf[mt][3]);
                    lA[mt] += p0 + p1;
                    lB[mt] += p2 + p3;
                    pfh[mt][hhf * 2]     = pack_h2(p0, p1);
                    pfh[mt][hhf * 2 + 1] = pack_h2(p2, p3);
                }
            }
            // ---- O += P.v for keys [s*16, s*16+16) ----
            #pragma unroll
            for (int nt = 0; nt < 4; nt++) {
                uint32_t voff = bofs + (uint32_t)((s * 16 + lane) * ROWB + nt * 16);
                uint32_t v0f, v1f;
                LDMX2T(v0f, v1f, sv0 + voff);
                #pragma unroll
                for (int mt = 0; mt < 2; mt++)
                    mma_f16(of[mt][nt], pfh[mt], v0f, v1f);
            }
        }
        __syncthreads();
    }

    // ---- normalize + write g_ao [m][c] fp16 single (proj A-side) ----
    const int bb = bh / NHEAD, hh = bh % NHEAD;
    #pragma unroll
    for (int mt = 0; mt < 2; mt++) {
        float a = lA[mt], b2 = lB[mt];
        a  += __shfl_xor_sync(0xffffffffu, a, 1);
        a  += __shfl_xor_sync(0xffffffffu, a, 2);
        b2 += __shfl_xor_sync(0xffffffffu, b2, 1);
        b2 += __shfl_xor_sync(0xffffffffu, b2, 2);
        const float ia = 1.f / a, ib = 1.f / b2;
        const int rA = n0 + w * 32 + mt * 16 + g;
        const size_t baseA = ((size_t)(bb * NN) + rA) * CDIM + hh * DHEAD;
        const size_t baseB = baseA + (size_t)8 * CDIM;
        #pragma unroll
        for (int nt = 0; nt < 4; nt++) {
            int col = nt * 8 + t4 * 2;
            *(uint32_t*)(g_ao + baseA + col) =
                pack_h2(of[mt][nt][0] * ia, of[mt][nt][1] * ia);
            *(uint32_t*)(g_ao + baseB + col) =
                pack_h2(of[mt][nt][2] * ib, of[mt][nt][3] * ib);
        }
    }
}

// ---------------------------------------------------------------------------
// Kernel 3: projection GEMM, fp16 2-term: out = ao_f16 . (pwh + pwl) + bias.
// Tile 128m x 128o, 256 threads (R15 verified config).
// ---------------------------------------------------------------------------
__global__ __launch_bounds__(256) void proj_mma(const float* __restrict__ bias,
                                                float* __restrict__ out) {
    __shared__ __align__(16) char sA [128 * GROWB];
    __shared__ __align__(16) char sBh[128 * GROWB], sBl[128 * GROWB];

    const int tid  = threadIdx.x;
    const int w    = tid >> 5, lane = tid & 31;
    const int mw   = w & 1,   ow   = w >> 1;
    const int m0   = blockIdx.x * 128;
    const int o0   = blockIdx.y * 128;
    const int b    = m0 >> 10;

    const uint32_t a_s  = smem_u32(sA);
    const uint32_t bh_s = smem_u32(sBh), bl_s = smem_u32(sBl);

    float acc[4][4][4];
    #pragma unroll
    for (int mt = 0; mt < 4; mt++)
        #pragma unroll
        for (int nt = 0; nt < 4; nt++)
            #pragma unroll
            for (int e = 0; e < 4; e++) acc[mt][nt][e] = 0.f;

    for (int it = 0; it < CDIM / 32; it++) {
        const int k0 = it * 32;
        __syncthreads();
        #pragma unroll
        for (int r = 0; r < 2; r++) {
            int idx = tid + 256 * r;
            int row = idx >> 2, c4 = idx & 3;
            size_t ga = (size_t)(m0 + row) * CDIM + k0 + c4 * 8;
            size_t gb = (size_t)(o0 + row) * CDIM + k0 + c4 * 8;
            *(uint4*)(sA  + row * GROWB + c4 * 16) = *(const uint4*)(g_ao  + ga);
            *(uint4*)(sBh + row * GROWB + c4 * 16) = *(const uint4*)(g_pwh + gb);
            *(uint4*)(sBl + row * GROWB + c4 * 16) = *(const uint4*)(g_pwl + gb);
        }
        __syncthreads();

        #pragma unroll
        for (int ks = 0; ks < 2; ks++) {
            uint32_t ah[4][4];
            const uint32_t aoff = (uint32_t)((mw * 64 + (lane & 15)) * GROWB
                                             + (ks * 16 + (lane >> 4) * 8) * 2);
            #pragma unroll
            for (int mt = 0; mt < 4; mt++)
                LDMX4(ah[mt], a_s + aoff + mt * 16 * GROWB);
            const uint32_t boff = (uint32_t)((ow * 32 + (lane & 7)) * GROWB
                                             + (ks * 16 + ((lane >> 3) & 1) * 8) * 2);
            #pragma unroll
            for (int nt = 0; nt < 4; nt++) {
                uint32_t b0, b1, c0r, c1;
                LDMX2(b0, b1, bh_s + boff + nt * 8 * GROWB);
                LDMX2(c0r, c1, bl_s + boff + nt * 8 * GROWB);
                #pragma unroll
                for (int mt = 0; mt < 4; mt++) {
                    mma_f16(acc[mt][nt], ah[mt], b0, b1);
                    mma_f16(acc[mt][nt], ah[mt], c0r, c1);
                }
            }
        }
    }

    // Epilogue: out[b][o][n] = acc + bias[o]
    const int g = lane >> 2, t4 = lane & 3;
    #pragma unroll
    for (int nt = 0; nt < 4; nt++) {
        const int o = o0 + ow * 32 + nt * 8 + t4 * 2;
        const float b0v = bias[o], b1v = bias[o + 1];
        float* r0 = out + ((size_t)b * CDIM + o) * NN;
        float* r1 = r0 + NN;
        #pragma unroll
        for (int mt = 0; mt < 4; mt++) {
            const int n = (m0 + mw * 64 + mt * 16 + g) & (NN - 1);
            float* ac = acc[mt][nt];
            r0[n]     = ac[0] + b0v;
            r1[n]     = ac[1] + b1v;
            r0[n + 8] = ac[2] + b0v;
            r1[n + 8] = ac[3] + b1v;
        }
    }
}

// ---------------------------------------------------------------------------
extern "C" void kernel_launch(void* const* d_in, const int* in_sizes, int n_in,
                              void* d_out, int out_size) {
    const float* x      = (const float*)d_in[0];   // [16,384,32,32]
    const float* qkv_w  = (const float*)d_in[1];   // [1152,384]
    const float* proj_w = (const float*)d_in[2];   // [384,384]
    const float* proj_b = (const float*)d_in[3];   // [384]
    float* out = (float*)d_out;                    // [16,384,32,32]

    convert_x<<<dim3(NN / 32, CDIM / 32, NB), dim3(32, 8)>>>(x);
    convert_w<<<(3 * CDIM * CDIM + 255) / 256, 256>>>(qkv_w, proj_w);
    qkv_mma<<<dim3(MT / 128, (3 * CDIM) / 128), 256>>>();
    attn_mma<<<dim3(NN / 128, NB * NHEAD), 128>>>();
    proj_mma<<<dim3(MT / 128, CDIM / 128), 256>>>(proj_b, out);
}